// round 6
// baseline (speedup 1.0000x reference)
#include <cuda_runtime.h>
#include <cuda_bf16.h>
#include <cstdint>
#include <cstddef>

// ---------------------------------------------------------------------------
// Fixed problem dims
// ---------------------------------------------------------------------------
static constexpr int E8   = 8;
static constexpr int MDIM = 1024;
static constexpr int KDIM = 2048;   // K of both GEMMs
static constexpr int N1   = 4096;   // N of GEMM1
static constexpr int N2   = 2048;   // N of GEMM2

static constexpr float ALPHA_C = 1.702f;
static constexpr float LIMIT_C = 7.0f;

// Scratch for the activated intermediate [E][1024][2048] (fp32)
__device__ float g_act[(size_t)E8 * MDIM * KDIM];

#define DEV_INLINE __device__ __forceinline__

DEV_INLINE uint32_t smem_u32(const void* p) {
    uint32_t a;
    asm("{ .reg .u64 t; cvta.to.shared.u64 t, %1; cvt.u32.u64 %0, t; }" : "=r"(a) : "l"(p));
    return a;
}

// Round-to-nearest fp32 -> tf32 (bit pattern in a u32 register for mma.sync)
DEV_INLINE uint32_t rna_tf32_u(float x) {
    uint32_t u;
    asm("cvt.rna.tf32.f32 %0, %1;" : "=r"(u) : "f"(x));
    return u;
}

DEV_INLINE float lds_f32(uint32_t a) {
    float v;
    asm volatile("ld.shared.f32 %0, [%1];" : "=f"(v) : "r"(a));
    return v;
}

DEV_INLINE void cp16(uint32_t dst, const void* src) {
    asm volatile("cp.async.cg.shared.global [%0], [%1], 16;" :: "r"(dst), "l"(src) : "memory");
}
DEV_INLINE void cp_commit() { asm volatile("cp.async.commit_group;" ::: "memory"); }
DEV_INLINE void cp_wait2()  { asm volatile("cp.async.wait_group 2;" ::: "memory"); }

// m16n8k8 tf32 mma, fp32 accumulate (sm_80+, no arch-specific 'a' features)
DEV_INLINE void mma8(float* c, const uint32_t* a, const uint32_t* b) {
    asm volatile(
        "mma.sync.aligned.m16n8k8.row.col.f32.tf32.tf32.f32 "
        "{%0,%1,%2,%3}, {%4,%5,%6,%7}, {%8,%9}, {%0,%1,%2,%3};"
        : "+f"(c[0]), "+f"(c[1]), "+f"(c[2]), "+f"(c[3])
        : "r"(a[0]), "r"(a[1]), "r"(a[2]), "r"(a[3]), "r"(b[0]), "r"(b[1]));
}

DEV_INLINE float glu_act(float g, float u) {
    g = fminf(g, LIMIT_C);
    u = fminf(fmaxf(u, -LIMIT_C), LIMIT_C);
    float s = 1.0f / (1.0f + __expf(-ALPHA_C * g));
    return (u + 1.0f) * (g * s);
}

// ---------------------------------------------------------------------------
// GEMM config: CTA tile 128x256, BK=32, 3-stage cp.async pipeline.
// 8 warps, each computes a 64x64 register tile (2 m-warps x 4 n-warps).
// A [E][M][K] K-contiguous.  B [E][K][N] N-contiguous (weights used directly,
// no transpose: mma.sync B-fragments are register-resident).
// SMEM As: [128 m][32 k] fp32, 128B rows, XOR-16B swizzle by (m&7)  -> both
//          cp.async 16B writes and 4B fragment reads are conflict-free.
// SMEM Bs: [32 k][256 n] fp32, 1KB rows, XOR-32B swizzle by (k&3)   -> same.
// ---------------------------------------------------------------------------
static constexpr int BM = 128, BN = 256, BK = 32, STAGES = 3;
static constexpr int ABYTES = BM * BK * 4;              // 16384
static constexpr int STAGE  = ABYTES + BK * BN * 4;     // 49152
static constexpr int SMEM_BYTES = STAGES * STAGE + 1024;

template <bool GLU>
__global__ void __launch_bounds__(256, 1)
gemm_tf32(const float* __restrict__ A, const float* __restrict__ B,
          const float* __restrict__ bias, float* __restrict__ out, int Ntot) {
    extern __shared__ char dynsm[];
    const uint32_t base = (smem_u32(dynsm) + 1023u) & ~1023u;
    const int tid = threadIdx.x, wid = tid >> 5, lane = tid & 31;
    const int grp = lane >> 2, tid4 = lane & 3;
    const int e = blockIdx.z, m0 = blockIdx.y * BM, n0 = blockIdx.x * BN;
    const int m_base = (wid & 1) * 64;     // warp m-origin in tile
    const int n_base = (wid >> 1) * 64;    // warp n-origin in tile

    const float* Ae = A + ((size_t)e * MDIM + m0) * KDIM;
    const float* Be = B + (size_t)e * KDIM * Ntot + n0;

    float acc[4][8][4];
    #pragma unroll
    for (int i = 0; i < 4; i++)
        #pragma unroll
        for (int j = 0; j < 8; j++)
            #pragma unroll
            for (int q = 0; q < 4; q++) acc[i][j][q] = 0.0f;

    // ---- stage loader: A 1024 chunks(16B), B 2048 chunks; 12 cp16/thread ----
    auto load_stage = [&](int buf, int kt) {
        const uint32_t sa = base + buf * STAGE, sb = sa + ABYTES;
        const float* ga = Ae + kt * BK;
        const float* gb = Be + (size_t)(kt * BK) * Ntot;
        #pragma unroll
        for (int i = 0; i < 4; i++) {
            int idx = tid + (i << 8);
            int r = idx >> 3, c = idx & 7;
            uint32_t d = sa + (uint32_t)(r * 128 + ((c * 16) ^ ((r & 7) * 16)));
            cp16(d, ga + (size_t)r * KDIM + c * 4);
        }
        #pragma unroll
        for (int i = 0; i < 8; i++) {
            int idx = tid + (i << 8);
            int k = idx >> 6, c = idx & 63;
            uint32_t d = sb + (uint32_t)(k * 1024 + ((c * 16) ^ ((k & 3) * 32)));
            cp16(d, gb + (size_t)k * Ntot + c * 4);
        }
    };

    // ---- one BK=32 chunk of MMAs from stage buf ----
    auto compute = [&](int buf) {
        const uint32_t sa = base + buf * STAGE, sb = sa + ABYTES;
        const uint32_t g16 = (uint32_t)(grp * 16);
        const uint32_t bx  = (uint32_t)(tid4 * 32);
        #pragma unroll
        for (int ks = 0; ks < 4; ks++) {
            const int kk = ks * 8;
            uint32_t a[4][4], b[8][2];
            const uint32_t kc0 = ((uint32_t)((kk + tid4) * 4)) ^ g16;
            const uint32_t kc1 = ((uint32_t)((kk + tid4 + 4) * 4)) ^ g16;
            #pragma unroll
            for (int t = 0; t < 4; t++) {
                uint32_t row = sa + (uint32_t)((m_base + t * 16 + grp) * 128);
                a[t][0] = rna_tf32_u(lds_f32(row + kc0));
                a[t][1] = rna_tf32_u(lds_f32(row + 1024 + kc0));   // +8 rows
                a[t][2] = rna_tf32_u(lds_f32(row + kc1));
                a[t][3] = rna_tf32_u(lds_f32(row + 1024 + kc1));
            }
            const uint32_t kb0 = sb + (uint32_t)((kk + tid4) * 1024);
            #pragma unroll
            for (int t = 0; t < 8; t++) {
                uint32_t cn = ((uint32_t)((n_base + t * 8 + grp) * 4)) ^ bx;
                b[t][0] = rna_tf32_u(lds_f32(kb0 + cn));
                b[t][1] = rna_tf32_u(lds_f32(kb0 + 4096 + cn));    // k+4 rows
            }
            #pragma unroll
            for (int i = 0; i < 4; i++)
                #pragma unroll
                for (int j = 0; j < 8; j++) mma8(acc[i][j], a[i], b[j]);
        }
    };

    // ---- pipeline: 64 K-chunks ----
    load_stage(0, 0); cp_commit();
    load_stage(1, 1); cp_commit();

    #pragma unroll 1
    for (int kt = 0; kt < 64; kt++) {
        __syncthreads();                       // everyone done with buffer (kt-1)%3
        if (kt + 2 < 64) load_stage((kt + 2) % 3, kt + 2);
        cp_commit();
        cp_wait2();                            // stage kt has landed (for this thread)
        __syncthreads();                       // ... and for every thread
        compute(kt % 3);
    }
    __syncthreads();                           // done: stage SMEM reusable for epilogue

    float* Cs = (float*)(dynsm + (base - smem_u32(dynsm)));
    const float* be = bias + (size_t)e * Ntot;

    if (GLU) {
        // acc cols (tid4*2, tid4*2+1) are an adjacent (even, odd) = (gate, up) pair
        const int P = 132;
        #pragma unroll
        for (int i = 0; i < 4; i++) {
            int row = m_base + i * 16 + grp;
            #pragma unroll
            for (int j = 0; j < 8; j++) {
                int col2 = n_base + j * 8 + tid4 * 2;
                float bg = be[n0 + col2], bu = be[n0 + col2 + 1];
                Cs[row * P + (col2 >> 1)]       = glu_act(acc[i][j][0] + bg, acc[i][j][1] + bu);
                Cs[(row + 8) * P + (col2 >> 1)] = glu_act(acc[i][j][2] + bg, acc[i][j][3] + bu);
            }
        }
        __syncthreads();
        // coalesced float4 writeback of 128x128 act tile; act pitch = 2048
        for (int idx = tid; idx < BM * 32; idx += 256) {
            int r = idx >> 5, q = idx & 31;
            float4 v = *(const float4*)(Cs + r * P + q * 4);
            *(float4*)(out + ((size_t)e * MDIM + m0 + r) * 2048 + (n0 >> 1) + q * 4) = v;
        }
    } else {
        const int P = 260;
        #pragma unroll
        for (int i = 0; i < 4; i++) {
            int row = m_base + i * 16 + grp;
            #pragma unroll
            for (int j = 0; j < 8; j++) {
                int col = n_base + j * 8 + tid4 * 2;
                Cs[row * P + col]           = acc[i][j][0];
                Cs[row * P + col + 1]       = acc[i][j][1];
                Cs[(row + 8) * P + col]     = acc[i][j][2];
                Cs[(row + 8) * P + col + 1] = acc[i][j][3];
            }
        }
        __syncthreads();
        // coalesced float4 writeback of 128x256 tile with bias; out pitch = 2048
        for (int idx = tid; idx < BM * 64; idx += 256) {
            int r = idx >> 6, q = idx & 63;
            float4 v = *(const float4*)(Cs + r * P + q * 4);
            float4 bb = *(const float4*)(be + n0 + q * 4);
            v.x += bb.x; v.y += bb.y; v.z += bb.z; v.w += bb.w;
            *(float4*)(out + ((size_t)e * MDIM + m0 + r) * 2048 + n0 + q * 4) = v;
        }
    }
}

// ---------------------------------------------------------------------------
// Launch: GEMM1(+GLU) -> g_act, then GEMM2(+bias) -> out. No prep kernels:
// tf32 rounding happens per-fragment in registers.
// ---------------------------------------------------------------------------
extern "C" void kernel_launch(void* const* d_in, const int* in_sizes, int n_in,
                              void* d_out, int out_size) {
    (void)in_sizes; (void)n_in; (void)out_size;
    const float* X  = (const float*)d_in[0];   // dispatched [1,1,E,1024,2048]
    const float* w1 = (const float*)d_in[1];   // [E,2048,4096]
    const float* b1 = (const float*)d_in[2];   // [E,4096]
    const float* w2 = (const float*)d_in[3];   // [E,2048,2048]
    const float* b2 = (const float*)d_in[4];   // [E,2048]
    float* out = (float*)d_out;                // [E,1,1024,2048]

    float* act;
    cudaGetSymbolAddress((void**)&act, g_act);

    cudaFuncSetAttribute(gemm_tf32<true>,
                         cudaFuncAttributeMaxDynamicSharedMemorySize, SMEM_BYTES);
    cudaFuncSetAttribute(gemm_tf32<false>,
                         cudaFuncAttributeMaxDynamicSharedMemorySize, SMEM_BYTES);

    gemm_tf32<true><<<dim3(N1 / BN, MDIM / BM, E8), 256, SMEM_BYTES>>>(X, w1, b1, act, N1);
    gemm_tf32<false><<<dim3(N2 / BN, MDIM / BM, E8), 256, SMEM_BYTES>>>(act, w2, b2, out, N2);
}

// round 7
// speedup vs baseline: 1.5725x; 1.5725x over previous
#include <cuda_runtime.h>
#include <cuda_fp16.h>
#include <cstdint>
#include <cstddef>

// ---------------------------------------------------------------------------
// Fixed problem dims
// ---------------------------------------------------------------------------
static constexpr int E8   = 8;
static constexpr int MDIM = 1024;
static constexpr int KDIM = 2048;   // K of both GEMMs
static constexpr int N1   = 4096;   // N of GEMM1
static constexpr int N2   = 2048;   // N of GEMM2

static constexpr float ALPHA_C = 1.702f;
static constexpr float LIMIT_C = 7.0f;

// ---------------------------------------------------------------------------
// Device scratch (static: no allocations allowed)
// ---------------------------------------------------------------------------
__device__ __half g_xh [(size_t)E8 * MDIM * KDIM];   //  32 MB  X  fp16
__device__ __half g_w1h[(size_t)E8 * KDIM * N1];     // 128 MB  w1 fp16
__device__ __half g_w2h[(size_t)E8 * KDIM * N2];     //  64 MB  w2 fp16
__device__ __half g_act[(size_t)E8 * MDIM * KDIM];   //  32 MB  activated fp16

#define DEV_INLINE __device__ __forceinline__

DEV_INLINE uint32_t smem_u32(const void* p) {
    uint32_t a;
    asm("{ .reg .u64 t; cvta.to.shared.u64 t, %1; cvt.u32.u64 %0, t; }" : "=r"(a) : "l"(p));
    return a;
}

DEV_INLINE void cp16(uint32_t dst, const void* src) {
    asm volatile("cp.async.cg.shared.global [%0], [%1], 16;" :: "r"(dst), "l"(src) : "memory");
}
DEV_INLINE void cp_commit() { asm volatile("cp.async.commit_group;" ::: "memory"); }
DEV_INLINE void cp_wait3()  { asm volatile("cp.async.wait_group 3;" ::: "memory"); }

DEV_INLINE void ldm_x4(uint32_t* r, uint32_t addr) {
    asm volatile("ldmatrix.sync.aligned.m8n8.x4.shared.b16 {%0,%1,%2,%3}, [%4];"
                 : "=r"(r[0]), "=r"(r[1]), "=r"(r[2]), "=r"(r[3]) : "r"(addr));
}
DEV_INLINE void ldm_x4t(uint32_t* r, uint32_t addr) {
    asm volatile("ldmatrix.sync.aligned.m8n8.x4.trans.shared.b16 {%0,%1,%2,%3}, [%4];"
                 : "=r"(r[0]), "=r"(r[1]), "=r"(r[2]), "=r"(r[3]) : "r"(addr));
}

// m16n8k16 fp16 mma, fp32 accumulate (sm_80+)
DEV_INLINE void mma16(float* c, const uint32_t* a, const uint32_t* b) {
    asm volatile(
        "mma.sync.aligned.m16n8k16.row.col.f32.f16.f16.f32 "
        "{%0,%1,%2,%3}, {%4,%5,%6,%7}, {%8,%9}, {%0,%1,%2,%3};"
        : "+f"(c[0]), "+f"(c[1]), "+f"(c[2]), "+f"(c[3])
        : "r"(a[0]), "r"(a[1]), "r"(a[2]), "r"(a[3]), "r"(b[0]), "r"(b[1]));
}

DEV_INLINE float glu_act(float g, float u) {
    g = fminf(g, LIMIT_C);
    u = fminf(fmaxf(u, -LIMIT_C), LIMIT_C);
    float s = 1.0f / (1.0f + __expf(-ALPHA_C * g));
    return (u + 1.0f) * (g * s);
}

// ---------------------------------------------------------------------------
// fp32 -> fp16 convert (float4 in, 4 halves out)
// ---------------------------------------------------------------------------
__global__ void __launch_bounds__(256) cvt_f16_kernel(const float4* __restrict__ src,
                                                      uint2* __restrict__ dst) {
    int i = blockIdx.x * 256 + threadIdx.x;
    float4 v = src[i];
    __half2 h0 = __floats2half2_rn(v.x, v.y);
    __half2 h1 = __floats2half2_rn(v.z, v.w);
    uint2 o;
    o.x = *(uint32_t*)&h0;
    o.y = *(uint32_t*)&h1;
    dst[i] = o;
}

// ---------------------------------------------------------------------------
// fp16 GEMM, CTA tile 128x256, BK=32, 4-stage cp.async, ldmatrix mainloop.
// A [E][1024][2048] fp16 K-contiguous.  B [E][2048][Ntot] fp16 N-contiguous.
// 8 warps, 64x64 register tile each (acc 4x8 m16n8 fragments).
//
// SMEM A stage: [128 m][32 k] fp16, row 64B = 4 x 16B units.
//   phys = m*64 + ((kb ^ ((m>>1)&3)) << 4)    (conflict-free cp16 + ldmatrix)
// SMEM B stage: [32 k][256 n] fp16, row 512B = 32 x 16B units.
//   phys = k*512 + ((nb ^ (k&7)) << 4)
// GLU=true : +bias, clipped-SiLU GLU on (even,odd) pairs, fp16 out (pitch 2048)
// GLU=false: +bias, fp32 out (pitch 2048)
// ---------------------------------------------------------------------------
static constexpr int BM = 128, BN = 256, BK = 32;
static constexpr int ABYTES = BM * BK * 2;          // 8192
static constexpr int STAGE  = ABYTES + BK * BN * 2; // 24576
static constexpr int SMEM_BYTES = 134656;           // max(4*STAGE, 128*260*4) + slack

template <bool GLU>
__global__ void __launch_bounds__(256, 1)
gemm_f16(const __half* __restrict__ A, const __half* __restrict__ B,
         const float* __restrict__ bias, void* __restrict__ outv, int Ntot) {
    extern __shared__ char dynsm[];
    const uint32_t base = (smem_u32(dynsm) + 1023u) & ~1023u;
    const int tid = threadIdx.x, wid = tid >> 5, lane = tid & 31;
    const int grp = lane >> 2, tid4 = lane & 3;
    const int e = blockIdx.z, m0 = blockIdx.y * BM, n0 = blockIdx.x * BN;
    const int m_base = (wid & 1) * 64;
    const int n_base = (wid >> 1) * 64;

    const __half* Ae = A + ((size_t)e * MDIM + m0) * KDIM;
    const __half* Be = B + (size_t)e * KDIM * Ntot + n0;

    float acc[4][8][4];
    #pragma unroll
    for (int i = 0; i < 4; i++)
        #pragma unroll
        for (int j = 0; j < 8; j++)
            #pragma unroll
            for (int q = 0; q < 4; q++) acc[i][j][q] = 0.0f;

    // per-thread ldmatrix lane addressing invariants
    const int rowL = lane & 15;          // A row / B k within fragment
    const int uL   = lane >> 4;          // 16B-unit select
    uint32_t aoff[4]; int sA[4];
    #pragma unroll
    for (int t = 0; t < 4; t++) {
        int rA = m_base + t * 16 + rowL;
        aoff[t] = (uint32_t)(rA * 64);
        sA[t] = (rA >> 1) & 3;
    }
    const int kB = rowL;                 // B row (k) for ldmatrix
    uint32_t nbp[4];
    #pragma unroll
    for (int p = 0; p < 4; p++)
        nbp[p] = (uint32_t)((((n_base >> 3) + 2 * p + uL) ^ (kB & 7)) << 4);
    const uint32_t bko = (uint32_t)(kB * 512);

    // ---- stage loader: A 2 chunks/thread, B 4 chunks/thread ----
    auto load_stage = [&](int buf, int kt) {
        const uint32_t sa = base + buf * STAGE, sb = sa + ABYTES;
        const __half* ga = Ae + kt * BK;
        const __half* gb = Be + (size_t)(kt * BK) * Ntot;
        #pragma unroll
        for (int i = 0; i < 2; i++) {
            int c = tid + (i << 8);
            int m = c >> 2, kb = c & 3;
            cp16(sa + (uint32_t)(m * 64 + ((kb ^ ((m >> 1) & 3)) << 4)),
                 ga + (size_t)m * KDIM + kb * 8);
        }
        #pragma unroll
        for (int i = 0; i < 4; i++) {
            int c = tid + (i << 8);
            int k = c >> 5, nb = c & 31;
            cp16(sb + (uint32_t)(k * 512 + ((nb ^ (k & 7)) << 4)),
                 gb + (size_t)k * Ntot + nb * 8);
        }
    };

    // ---- one BK=32 chunk: 2 x (K=16): 8 ldmatrix + 32 mma per ks ----
    auto compute = [&](int buf) {
        const uint32_t sa = base + buf * STAGE, sb = sa + ABYTES;
        #pragma unroll
        for (int ks = 0; ks < 2; ks++) {
            const int kb0 = ks * 2;
            uint32_t a[4][4], b[8][2];
            #pragma unroll
            for (int t = 0; t < 4; t++)
                ldm_x4(a[t], sa + aoff[t] + (uint32_t)((((kb0 + uL) ^ sA[t])) << 4));
            const uint32_t sbk = sb + (uint32_t)(ks * 16 * 512) + bko;
            #pragma unroll
            for (int p = 0; p < 4; p++) {
                uint32_t r[4];
                ldm_x4t(r, sbk + nbp[p]);
                b[2 * p][0] = r[0]; b[2 * p][1] = r[1];
                b[2 * p + 1][0] = r[2]; b[2 * p + 1][1] = r[3];
            }
            #pragma unroll
            for (int i = 0; i < 4; i++)
                #pragma unroll
                for (int j = 0; j < 8; j++) mma16(acc[i][j], a[i], b[j]);
        }
    };

    // ---- pipeline: 64 K-chunks, 4 stages ----
    load_stage(0, 0); cp_commit();
    load_stage(1, 1); cp_commit();
    load_stage(2, 2); cp_commit();

    #pragma unroll 1
    for (int kt = 0; kt < 64; kt++) {
        __syncthreads();                        // all warps done with buf (kt-1)&3
        if (kt + 3 < 64) load_stage((kt + 3) & 3, kt + 3);
        cp_commit();
        cp_wait3();                             // stage kt landed (this thread)
        __syncthreads();                        // ... and for all threads
        compute(kt & 3);
    }
    __syncthreads();                            // SMEM reusable for epilogue

    float* Cs = (float*)(dynsm + (base - smem_u32(dynsm)));
    const float* be = bias + (size_t)e * Ntot;

    if (GLU) {
        __half* out = (__half*)outv;
        const int P = 132;
        #pragma unroll
        for (int i = 0; i < 4; i++) {
            int row = m_base + i * 16 + grp;
            #pragma unroll
            for (int j = 0; j < 8; j++) {
                int col2 = n_base + j * 8 + tid4 * 2;
                float bg = be[n0 + col2], bu = be[n0 + col2 + 1];
                Cs[row * P + (col2 >> 1)]       = glu_act(acc[i][j][0] + bg, acc[i][j][1] + bu);
                Cs[(row + 8) * P + (col2 >> 1)] = glu_act(acc[i][j][2] + bg, acc[i][j][3] + bu);
            }
        }
        __syncthreads();
        // fp16 writeback of 128x128 act tile; act row pitch 2048 halves
        for (int idx = tid; idx < BM * 32; idx += 256) {
            int r = idx >> 5, q = idx & 31;
            float4 v = *(const float4*)(Cs + r * P + q * 4);
            __half2 h0 = __floats2half2_rn(v.x, v.y);
            __half2 h1 = __floats2half2_rn(v.z, v.w);
            uint2 o; o.x = *(uint32_t*)&h0; o.y = *(uint32_t*)&h1;
            *(uint2*)(out + ((size_t)e * MDIM + m0 + r) * 2048 + (n0 >> 1) + q * 4) = o;
        }
    } else {
        float* out = (float*)outv;
        const int P = 260;
        #pragma unroll
        for (int i = 0; i < 4; i++) {
            int row = m_base + i * 16 + grp;
            #pragma unroll
            for (int j = 0; j < 8; j++) {
                int col = n_base + j * 8 + tid4 * 2;
                Cs[row * P + col]           = acc[i][j][0];
                Cs[row * P + col + 1]       = acc[i][j][1];
                Cs[(row + 8) * P + col]     = acc[i][j][2];
                Cs[(row + 8) * P + col + 1] = acc[i][j][3];
            }
        }
        __syncthreads();
        for (int idx = tid; idx < BM * 64; idx += 256) {
            int r = idx >> 6, q = idx & 63;
            float4 v = *(const float4*)(Cs + r * P + q * 4);
            float4 bb = *(const float4*)(be + n0 + q * 4);
            v.x += bb.x; v.y += bb.y; v.z += bb.z; v.w += bb.w;
            *(float4*)(out + ((size_t)e * MDIM + m0 + r) * 2048 + n0 + q * 4) = v;
        }
    }
}

// ---------------------------------------------------------------------------
// Launch: convert X/w1/w2 to fp16, GEMM1(+GLU)->act(fp16), GEMM2(+bias)->out
// ---------------------------------------------------------------------------
extern "C" void kernel_launch(void* const* d_in, const int* in_sizes, int n_in,
                              void* d_out, int out_size) {
    (void)in_sizes; (void)n_in; (void)out_size;
    const float* X  = (const float*)d_in[0];
    const float* w1 = (const float*)d_in[1];
    const float* b1 = (const float*)d_in[2];
    const float* w2 = (const float*)d_in[3];
    const float* b2 = (const float*)d_in[4];
    float* out = (float*)d_out;

    __half *xh, *w1h, *w2h, *act;
    cudaGetSymbolAddress((void**)&xh,  g_xh);
    cudaGetSymbolAddress((void**)&w1h, g_w1h);
    cudaGetSymbolAddress((void**)&w2h, g_w2h);
    cudaGetSymbolAddress((void**)&act, g_act);

    cudaFuncSetAttribute(gemm_f16<true>,
                         cudaFuncAttributeMaxDynamicSharedMemorySize, SMEM_BYTES);
    cudaFuncSetAttribute(gemm_f16<false>,
                         cudaFuncAttributeMaxDynamicSharedMemorySize, SMEM_BYTES);

    const size_t nX  = (size_t)E8 * MDIM * KDIM;   // 16M
    const size_t nW1 = (size_t)E8 * KDIM * N1;     // 64M
    const size_t nW2 = (size_t)E8 * KDIM * N2;     // 32M
    cvt_f16_kernel<<<(unsigned)(nX  / 4 / 256), 256>>>((const float4*)X,  (uint2*)xh);
    cvt_f16_kernel<<<(unsigned)(nW1 / 4 / 256), 256>>>((const float4*)w1, (uint2*)w1h);
    cvt_f16_kernel<<<(unsigned)(nW2 / 4 / 256), 256>>>((const float4*)w2, (uint2*)w2h);

    gemm_f16<true><<<dim3(N1 / BN, MDIM / BM, E8), 256, SMEM_BYTES>>>(xh, w1h, b1, act, N1);
    gemm_f16<false><<<dim3(N2 / BN, MDIM / BM, E8), 256, SMEM_BYTES>>>(act, w2h, b2, out, N2);
}

// round 8
// speedup vs baseline: 1.6898x; 1.0746x over previous
#include <cuda_runtime.h>
#include <cuda_fp16.h>
#include <cstdint>
#include <cstddef>

// ---------------------------------------------------------------------------
// Fixed problem dims
// ---------------------------------------------------------------------------
static constexpr int E8   = 8;
static constexpr int MDIM = 1024;
static constexpr int KDIM = 2048;   // K of both GEMMs
static constexpr int N1   = 4096;   // N of GEMM1
static constexpr int N2   = 2048;   // N of GEMM2

static constexpr float ALPHA_C = 1.702f;
static constexpr float LIMIT_C = 7.0f;

// ---------------------------------------------------------------------------
// Device scratch (static: no allocations allowed)
// ---------------------------------------------------------------------------
__device__ __half g_xh [(size_t)E8 * MDIM * KDIM];   //  32 MB  X  fp16
__device__ __half g_w1h[(size_t)E8 * KDIM * N1];     // 128 MB  w1 fp16
__device__ __half g_w2h[(size_t)E8 * KDIM * N2];     //  64 MB  w2 fp16
__device__ __half g_act[(size_t)E8 * MDIM * KDIM];   //  32 MB  activated fp16

#define DEV_INLINE __device__ __forceinline__

DEV_INLINE uint32_t smem_u32(const void* p) {
    uint32_t a;
    asm("{ .reg .u64 t; cvta.to.shared.u64 t, %1; cvt.u32.u64 %0, t; }" : "=r"(a) : "l"(p));
    return a;
}

DEV_INLINE void cp16(uint32_t dst, const void* src) {
    asm volatile("cp.async.cg.shared.global [%0], [%1], 16;" :: "r"(dst), "l"(src) : "memory");
}
DEV_INLINE void cp_commit() { asm volatile("cp.async.commit_group;" ::: "memory"); }
DEV_INLINE void cp_wait2()  { asm volatile("cp.async.wait_group 2;" ::: "memory"); }

DEV_INLINE void ldm_x4(uint32_t* r, uint32_t addr) {
    asm volatile("ldmatrix.sync.aligned.m8n8.x4.shared.b16 {%0,%1,%2,%3}, [%4];"
                 : "=r"(r[0]), "=r"(r[1]), "=r"(r[2]), "=r"(r[3]) : "r"(addr));
}
DEV_INLINE void ldm_x4t(uint32_t* r, uint32_t addr) {
    asm volatile("ldmatrix.sync.aligned.m8n8.x4.trans.shared.b16 {%0,%1,%2,%3}, [%4];"
                 : "=r"(r[0]), "=r"(r[1]), "=r"(r[2]), "=r"(r[3]) : "r"(addr));
}

// m16n8k16 fp16 mma, fp32 accumulate
DEV_INLINE void mma16(float* c, const uint32_t* a, const uint32_t* b) {
    asm volatile(
        "mma.sync.aligned.m16n8k16.row.col.f32.f16.f16.f32 "
        "{%0,%1,%2,%3}, {%4,%5,%6,%7}, {%8,%9}, {%0,%1,%2,%3};"
        : "+f"(c[0]), "+f"(c[1]), "+f"(c[2]), "+f"(c[3])
        : "r"(a[0]), "r"(a[1]), "r"(a[2]), "r"(a[3]), "r"(b[0]), "r"(b[1]));
}

DEV_INLINE float glu_act(float g, float u) {
    g = fminf(g, LIMIT_C);
    u = fminf(fmaxf(u, -LIMIT_C), LIMIT_C);
    float s = 1.0f / (1.0f + __expf(-ALPHA_C * g));
    return (u + 1.0f) * (g * s);
}

// ---------------------------------------------------------------------------
// fp32 -> fp16 convert
// ---------------------------------------------------------------------------
__global__ void __launch_bounds__(256) cvt_f16_kernel(const float4* __restrict__ src,
                                                      uint2* __restrict__ dst) {
    int i = blockIdx.x * 256 + threadIdx.x;
    float4 v = src[i];
    __half2 h0 = __floats2half2_rn(v.x, v.y);
    __half2 h1 = __floats2half2_rn(v.z, v.w);
    uint2 o;
    o.x = *(uint32_t*)&h0;
    o.y = *(uint32_t*)&h1;
    dst[i] = o;
}

// ---------------------------------------------------------------------------
// fp16 GEMM, CTA tile 128x256, BK=32, 4-stage cp.async, ldmatrix mainloop.
// 512 threads / 16 warps: 4 m-warps x 4 n-warps, warp tile 32x64.
// A [E][1024][2048] fp16 K-contiguous.  B [E][2048][Ntot] fp16 N-contiguous.
// SMEM A stage: [128 m][32 k] fp16, row 64B; phys = m*64 + ((kb ^ ((m>>1)&3))<<4)
// SMEM B stage: [32 k][256 n] fp16, row 512B; phys = k*512 + ((nb ^ (k&7))<<4)
// Single __syncthreads per K-chunk; loads for kt+3 issued before compute(kt).
// ---------------------------------------------------------------------------
static constexpr int BM = 128, BN = 256, BK = 32;
static constexpr int ABYTES = BM * BK * 2;          // 8192
static constexpr int STAGE  = ABYTES + BK * BN * 2; // 24576
static constexpr int SMEM_BYTES = 134656;           // max(4*STAGE, 128*260*4) + slack

template <bool GLU>
__global__ void __launch_bounds__(512, 1)
gemm_f16(const __half* __restrict__ A, const __half* __restrict__ B,
         const float* __restrict__ bias, void* __restrict__ outv, int Ntot) {
    extern __shared__ char dynsm[];
    const uint32_t base = (smem_u32(dynsm) + 1023u) & ~1023u;
    const int tid = threadIdx.x, wid = tid >> 5, lane = tid & 31;
    const int grp = lane >> 2, tid4 = lane & 3;
    const int e = blockIdx.z, m0 = blockIdx.y * BM, n0 = blockIdx.x * BN;
    const int m_base = (wid & 3) * 32;       // 4 m-warps
    const int n_base = (wid >> 2) * 64;      // 4 n-warps

    const __half* Ae = A + ((size_t)e * MDIM + m0) * KDIM;
    const __half* Be = B + (size_t)e * KDIM * Ntot + n0;

    float acc[2][8][4];
    #pragma unroll
    for (int i = 0; i < 2; i++)
        #pragma unroll
        for (int j = 0; j < 8; j++)
            #pragma unroll
            for (int q = 0; q < 4; q++) acc[i][j][q] = 0.0f;

    // per-thread ldmatrix lane invariants
    const int rowL = lane & 15;
    const int uL   = lane >> 4;
    uint32_t aoff[2]; int sA[2];
    #pragma unroll
    for (int t = 0; t < 2; t++) {
        int rA = m_base + t * 16 + rowL;
        aoff[t] = (uint32_t)(rA * 64);
        sA[t] = (rA >> 1) & 3;
    }
    const int kB = rowL;
    uint32_t nbp[4];
    #pragma unroll
    for (int p = 0; p < 4; p++)
        nbp[p] = (uint32_t)((((n_base >> 3) + 2 * p + uL) ^ (kB & 7)) << 4);
    const uint32_t bko = (uint32_t)(kB * 512);

    // ---- stage loader: A 1 chunk/thread, B 2 chunks/thread (512 threads) ----
    auto load_stage = [&](int buf, int kt) {
        const uint32_t sa = base + buf * STAGE, sb = sa + ABYTES;
        const __half* ga = Ae + kt * BK;
        const __half* gb = Be + (size_t)(kt * BK) * Ntot;
        {
            int m = tid >> 2, kb = tid & 3;
            cp16(sa + (uint32_t)(m * 64 + ((kb ^ ((m >> 1) & 3)) << 4)),
                 ga + (size_t)m * KDIM + kb * 8);
        }
        #pragma unroll
        for (int i = 0; i < 2; i++) {
            int c = tid + (i << 9);
            int k = c >> 5, nb = c & 31;
            cp16(sb + (uint32_t)(k * 512 + ((nb ^ (k & 7)) << 4)),
                 gb + (size_t)k * Ntot + nb * 8);
        }
    };

    // ---- one BK=32 chunk: 2 x (K=16): 6 ldmatrix + 16 mma per ks ----
    auto compute = [&](int buf) {
        const uint32_t sa = base + buf * STAGE, sb = sa + ABYTES;
        #pragma unroll
        for (int ks = 0; ks < 2; ks++) {
            const int kb0 = ks * 2;
            uint32_t a[2][4], b[8][2];
            #pragma unroll
            for (int t = 0; t < 2; t++)
                ldm_x4(a[t], sa + aoff[t] + (uint32_t)((((kb0 + uL) ^ sA[t])) << 4));
            const uint32_t sbk = sb + (uint32_t)(ks * 16 * 512) + bko;
            #pragma unroll
            for (int p = 0; p < 4; p++) {
                uint32_t r[4];
                ldm_x4t(r, sbk + nbp[p]);
                b[2 * p][0] = r[0]; b[2 * p][1] = r[1];
                b[2 * p + 1][0] = r[2]; b[2 * p + 1][1] = r[3];
            }
            #pragma unroll
            for (int i = 0; i < 2; i++)
                #pragma unroll
                for (int j = 0; j < 8; j++) mma16(acc[i][j], a[i], b[j]);
        }
    };

    // ---- pipeline: 64 K-chunks, 4 stages, one barrier per chunk ----
    load_stage(0, 0); cp_commit();
    load_stage(1, 1); cp_commit();
    load_stage(2, 2); cp_commit();

    #pragma unroll 1
    for (int kt = 0; kt < 64; kt++) {
        cp_wait2();                 // stage kt landed (this thread)
        __syncthreads();            // visible to all; all done with compute(kt-1)
        if (kt + 3 < 64) load_stage((kt + 3) & 3, kt + 3);
        cp_commit();
        compute(kt & 3);
    }
    __syncthreads();                // SMEM reusable for epilogue

    float* Cs = (float*)(dynsm + (base - smem_u32(dynsm)));
    const float* be = bias + (size_t)e * Ntot;

    if (GLU) {
        __half* out = (__half*)outv;
        const int P = 132;
        #pragma unroll
        for (int i = 0; i < 2; i++) {
            int row = m_base + i * 16 + grp;
            #pragma unroll
            for (int j = 0; j < 8; j++) {
                int col2 = n_base + j * 8 + tid4 * 2;
                float bg = be[n0 + col2], bu = be[n0 + col2 + 1];
                Cs[row * P + (col2 >> 1)]       = glu_act(acc[i][j][0] + bg, acc[i][j][1] + bu);
                Cs[(row + 8) * P + (col2 >> 1)] = glu_act(acc[i][j][2] + bg, acc[i][j][3] + bu);
            }
        }
        __syncthreads();
        // fp16 writeback of 128x128 act tile; act row pitch 2048 halves
        for (int idx = tid; idx < BM * 32; idx += 512) {
            int r = idx >> 5, q = idx & 31;
            float4 v = *(const float4*)(Cs + r * P + q * 4);
            __half2 h0 = __floats2half2_rn(v.x, v.y);
            __half2 h1 = __floats2half2_rn(v.z, v.w);
            uint2 o; o.x = *(uint32_t*)&h0; o.y = *(uint32_t*)&h1;
            *(uint2*)(out + ((size_t)e * MDIM + m0 + r) * 2048 + (n0 >> 1) + q * 4) = o;
        }
    } else {
        float* out = (float*)outv;
        const int P = 260;
        #pragma unroll
        for (int i = 0; i < 2; i++) {
            int row = m_base + i * 16 + grp;
            #pragma unroll
            for (int j = 0; j < 8; j++) {
                int col = n_base + j * 8 + tid4 * 2;
                Cs[row * P + col]           = acc[i][j][0];
                Cs[row * P + col + 1]       = acc[i][j][1];
                Cs[(row + 8) * P + col]     = acc[i][j][2];
                Cs[(row + 8) * P + col + 1] = acc[i][j][3];
            }
        }
        __syncthreads();
        for (int idx = tid; idx < BM * 64; idx += 512) {
            int r = idx >> 6, q = idx & 63;
            float4 v = *(const float4*)(Cs + r * P + q * 4);
            float4 bb = *(const float4*)(be + n0 + q * 4);
            v.x += bb.x; v.y += bb.y; v.z += bb.z; v.w += bb.w;
            *(float4*)(out + ((size_t)e * MDIM + m0 + r) * 2048 + n0 + q * 4) = v;
        }
    }
}

// ---------------------------------------------------------------------------
// Launch: convert X/w1/w2 to fp16, GEMM1(+GLU)->act(fp16), GEMM2(+bias)->out
// ---------------------------------------------------------------------------
extern "C" void kernel_launch(void* const* d_in, const int* in_sizes, int n_in,
                              void* d_out, int out_size) {
    (void)in_sizes; (void)n_in; (void)out_size;
    const float* X  = (const float*)d_in[0];
    const float* w1 = (const float*)d_in[1];
    const float* b1 = (const float*)d_in[2];
    const float* w2 = (const float*)d_in[3];
    const float* b2 = (const float*)d_in[4];
    float* out = (float*)d_out;

    __half *xh, *w1h, *w2h, *act;
    cudaGetSymbolAddress((void**)&xh,  g_xh);
    cudaGetSymbolAddress((void**)&w1h, g_w1h);
    cudaGetSymbolAddress((void**)&w2h, g_w2h);
    cudaGetSymbolAddress((void**)&act, g_act);

    cudaFuncSetAttribute(gemm_f16<true>,
                         cudaFuncAttributeMaxDynamicSharedMemorySize, SMEM_BYTES);
    cudaFuncSetAttribute(gemm_f16<false>,
                         cudaFuncAttributeMaxDynamicSharedMemorySize, SMEM_BYTES);

    const size_t nX  = (size_t)E8 * MDIM * KDIM;   // 16M
    const size_t nW1 = (size_t)E8 * KDIM * N1;     // 64M
    const size_t nW2 = (size_t)E8 * KDIM * N2;     // 32M
    cvt_f16_kernel<<<(unsigned)(nX  / 4 / 256), 256>>>((const float4*)X,  (uint2*)xh);
    cvt_f16_kernel<<<(unsigned)(nW1 / 4 / 256), 256>>>((const float4*)w1, (uint2*)w1h);
    cvt_f16_kernel<<<(unsigned)(nW2 / 4 / 256), 256>>>((const float4*)w2, (uint2*)w2h);

    gemm_f16<true><<<dim3(N1 / BN, MDIM / BM, E8), 512, SMEM_BYTES>>>(xh, w1h, b1, act, N1);
    gemm_f16<false><<<dim3(N2 / BN, MDIM / BM, E8), 512, SMEM_BYTES>>>(act, w2h, b2, out, N2);
}